// round 13
// baseline (speedup 1.0000x reference)
#include <cuda_runtime.h>
#include <cuda_bf16.h>
#include <cstdint>

// Problem constants (fixed by reference setup_inputs)
#define N_NODES 50000
#define D_IN    128
#define D_OUT   128
#define N_EDGES 800000

// Scratch: pre-activations for both weight matrices, interleaved per row:
// g_pre[row*256 + 0..127]   = x[row] @ W0
// g_pre[row*256 + 128..255] = x[row] @ W1
__device__ float g_pre[(size_t)N_NODES * 256];

// ---------------------------------------------------------------------------
// Kernel 1: zero the output accumulator (d_out is poisoned with 0xAA)
// ---------------------------------------------------------------------------
__global__ void zero_out_kernel(float4* __restrict__ out, int n4) {
    int i = blockIdx.x * blockDim.x + threadIdx.x;
    if (i < n4) out[i] = make_float4(0.f, 0.f, 0.f, 0.f);
}

// ---------------------------------------------------------------------------
// Kernel 2: SGEMM  pre[:, yTile*128 : +128] = x @ (yTile==0 ? W0 : W1)
// BM=128, BN=128, BK=16, 256 threads, 8x8 micro-tile per thread.
// ---------------------------------------------------------------------------
#define BM 128
#define BN 128
#define BK 16

__global__ __launch_bounds__(256, 2)
void gemm_kernel(const float* __restrict__ X,
                 const float* __restrict__ W0,
                 const float* __restrict__ W1) {
    __shared__ float As[BK][BM];   // A stored transposed: As[k][m]
    __shared__ float Bs[BK][BN];

    const int mTile = blockIdx.x * BM;
    const float* __restrict__ W = (blockIdx.y == 0) ? W0 : W1;
    const int nOff = blockIdx.y * 128;   // column offset into g_pre row (0 or 128)

    const int tid = threadIdx.x;
    const int tx = tid & 15;       // 0..15 -> col group (8 cols each)
    const int ty = tid >> 4;       // 0..15 -> row group (8 rows each)

    float acc[8][8];
#pragma unroll
    for (int i = 0; i < 8; i++)
#pragma unroll
        for (int j = 0; j < 8; j++) acc[i][j] = 0.f;

    // load indices for A tile: 128 rows x 16 cols = 512 float4, 2 per thread
    const int aRow0 = tid >> 2;          // 0..63
    const int aCol4 = (tid & 3) * 4;     // 0,4,8,12
    // load indices for B tile: 16 rows x 128 cols = 512 float4, 2 per thread
    const int bRow0 = tid >> 5;          // 0..7
    const int bCol4 = (tid & 31) * 4;    // 0..124

    for (int k0 = 0; k0 < D_IN; k0 += BK) {
        // ---- load A tile (with M bound guard), store transposed ----
#pragma unroll
        for (int h = 0; h < 2; h++) {
            int row = aRow0 + h * 64;
            int grow = mTile + row;
            float4 v = make_float4(0.f, 0.f, 0.f, 0.f);
            if (grow < N_NODES)
                v = *reinterpret_cast<const float4*>(X + (size_t)grow * D_IN + k0 + aCol4);
            As[aCol4 + 0][row] = v.x;
            As[aCol4 + 1][row] = v.y;
            As[aCol4 + 2][row] = v.z;
            As[aCol4 + 3][row] = v.w;
        }
        // ---- load B tile (K,N both exact multiples, no guard) ----
#pragma unroll
        for (int h = 0; h < 2; h++) {
            int krow = bRow0 + h * 8;
            float4 v = *reinterpret_cast<const float4*>(W + (size_t)(k0 + krow) * 128 + bCol4);
            *reinterpret_cast<float4*>(&Bs[krow][bCol4]) = v;
        }
        __syncthreads();

#pragma unroll
        for (int k = 0; k < BK; k++) {
            float4 a0 = *reinterpret_cast<const float4*>(&As[k][ty * 8]);
            float4 a1 = *reinterpret_cast<const float4*>(&As[k][ty * 8 + 4]);
            float4 b0 = *reinterpret_cast<const float4*>(&Bs[k][tx * 8]);
            float4 b1 = *reinterpret_cast<const float4*>(&Bs[k][tx * 8 + 4]);
            float a[8] = {a0.x, a0.y, a0.z, a0.w, a1.x, a1.y, a1.z, a1.w};
            float b[8] = {b0.x, b0.y, b0.z, b0.w, b1.x, b1.y, b1.z, b1.w};
#pragma unroll
            for (int i = 0; i < 8; i++)
#pragma unroll
                for (int j = 0; j < 8; j++)
                    acc[i][j] = fmaf(a[i], b[j], acc[i][j]);
        }
        __syncthreads();
    }

    // ---- store 8x8 micro-tile (cols contiguous -> 2x float4 per row) ----
#pragma unroll
    for (int i = 0; i < 8; i++) {
        int grow = mTile + ty * 8 + i;
        if (grow >= N_NODES) break;
        float* dst = g_pre + (size_t)grow * 256 + nOff + tx * 8;
        *reinterpret_cast<float4*>(dst)     = make_float4(acc[i][0], acc[i][1], acc[i][2], acc[i][3]);
        *reinterpret_cast<float4*>(dst + 4) = make_float4(acc[i][4], acc[i][5], acc[i][6], acc[i][7]);
    }
}

// ---------------------------------------------------------------------------
// Kernel 3: SpMM scatter — one warp per edge, float4 gather + red.v4 scatter.
// Handles both edge sets in one grid (warp id >= E -> set 1).
// ---------------------------------------------------------------------------
__device__ __forceinline__ void red_add_v4(float* addr, float4 v) {
    asm volatile("red.global.add.v4.f32 [%0], {%1, %2, %3, %4};"
                 :: "l"(addr), "f"(v.x), "f"(v.y), "f"(v.z), "f"(v.w)
                 : "memory");
}

__global__ __launch_bounds__(256)
void spmm_kernel(const float* __restrict__ vals0,
                 const float* __restrict__ vals1,
                 const int* __restrict__ idx0,
                 const int* __restrict__ idx1,
                 float* __restrict__ out) {
    const int gwarp = (blockIdx.x * blockDim.x + threadIdx.x) >> 5;
    const int lane  = threadIdx.x & 31;
    if (gwarp >= 2 * N_EDGES) return;

    const int set = (gwarp >= N_EDGES) ? 1 : 0;
    const int e   = gwarp - set * N_EDGES;
    const int* __restrict__ idx  = set ? idx1  : idx0;
    const float* __restrict__ vv = set ? vals1 : vals0;

    const int   dst = __ldg(idx + e);             // edge_index[0] = dst row
    const int   src = __ldg(idx + N_EDGES + e);   // edge_index[1] = src col
    const float v   = __ldg(vv + e);

    const float4 p = *reinterpret_cast<const float4*>(
        g_pre + (size_t)src * 256 + set * 128 + lane * 4);

    float4 r = make_float4(p.x * v, p.y * v, p.z * v, p.w * v);
    red_add_v4(out + (size_t)dst * D_OUT + lane * 4, r);
}

// ---------------------------------------------------------------------------
// Kernel 4: epilogue — out = relu(out + bias), in place, float4.
// ---------------------------------------------------------------------------
__global__ void epilogue_kernel(float4* __restrict__ out,
                                const float* __restrict__ bias, int n4) {
    int i = blockIdx.x * blockDim.x + threadIdx.x;
    if (i >= n4) return;
    int c = (i & 31) * 4;   // column group within the 128-wide row
    float4 v = out[i];
    v.x = fmaxf(v.x + __ldg(bias + c + 0), 0.f);
    v.y = fmaxf(v.y + __ldg(bias + c + 1), 0.f);
    v.z = fmaxf(v.z + __ldg(bias + c + 2), 0.f);
    v.w = fmaxf(v.w + __ldg(bias + c + 3), 0.f);
    out[i] = v;
}

// ---------------------------------------------------------------------------
// Launch
// Inputs (metadata order): x, W0, W1, bias, edge_vals0, edge_vals1,
//                          edge_index0, edge_index1
// ---------------------------------------------------------------------------
extern "C" void kernel_launch(void* const* d_in, const int* in_sizes, int n_in,
                              void* d_out, int out_size) {
    const float* x     = (const float*)d_in[0];
    const float* W0    = (const float*)d_in[1];
    const float* W1    = (const float*)d_in[2];
    const float* bias  = (const float*)d_in[3];
    const float* ev0   = (const float*)d_in[4];
    const float* ev1   = (const float*)d_in[5];
    const int*   ei0   = (const int*)d_in[6];
    const int*   ei1   = (const int*)d_in[7];
    float*       out   = (float*)d_out;

    const int n4 = N_NODES * D_OUT / 4;   // 1.6M float4

    // 1) zero output accumulator
    zero_out_kernel<<<(n4 + 255) / 256, 256>>>((float4*)out, n4);

    // 2) dense GEMM: pre = x @ [W0 | W1]
    dim3 gGrid((N_NODES + BM - 1) / BM, 2);
    gemm_kernel<<<gGrid, 256>>>(x, W0, W1);

    // 3) edge scatter: one warp per edge, both sets
    const int totalWarps = 2 * N_EDGES;
    spmm_kernel<<<(totalWarps * 32 + 255) / 256, 256>>>(ev0, ev1, ei0, ei1, out);

    // 4) bias + relu in place
    epilogue_kernel<<<(n4 + 255) / 256, 256>>>((float4*)out, bias, n4);
}